// round 6
// baseline (speedup 1.0000x reference)
#include <cuda_runtime.h>
#include <math.h>

#define B_  512
#define T_  512
#define H_  100
#define DI_ 101
#define DO_ 2

typedef unsigned long long ull;

__device__ float g_xp[(size_t)B_ * T_ * H_];

__device__ __forceinline__ ull fma2(ull a, ull b, ull c) {
    ull d;
    asm("fma.rn.f32x2 %0, %1, %2, %3;" : "=l"(d) : "l"(a), "l"(b), "l"(c));
    return d;
}
__device__ __forceinline__ ull dup2(float a) {
    ull d;
    asm("mov.b64 %0, {%1, %1};" : "=l"(d) : "f"(a));
    return d;
}
__device__ __forceinline__ float2 u2f(ull v) {
    float2 f;
    asm("mov.b64 {%0, %1}, %2;" : "=f"(f.x), "=f"(f.y) : "l"(v));
    return f;
}
__device__ __forceinline__ void cp_async4(unsigned smem_addr, const void* gptr) {
    asm volatile("cp.async.ca.shared.global [%0], [%1], 4;"
                 :: "r"(smem_addr), "l"(gptr));
}

// ---------------------------------------------------------------------------
// Kernel A: xp[r][j] = sum_i input[r][i] * W_x[j][i] + b[j]
// 256 threads, 64-row tiles, 8x4 microtile (rows FFMA2-packed).
// in_s DOUBLE-BUFFERED and filled with cp.async so the next tile's DRAM
// latency hides under the current tile's FFMA2 loop.
// ---------------------------------------------------------------------------
#define INS_STRIDE 68
__global__ void __launch_bounds__(256) xp_gemm_kernel(
    const float* __restrict__ inp,   // [B*T, DI]
    const float* __restrict__ Wx,    // [H, DI]
    const float* __restrict__ bias)  // [H]
{
    extern __shared__ __align__(16) float smem[];
    float* Wx_s = smem;                                 // [i][j]
    float* inb0 = smem + DI_ * H_;                      // buffer 0
    float* inb1 = smem + DI_ * H_ + DI_ * INS_STRIDE;   // buffer 1

    const int tid = threadIdx.x;
    const int tx  = tid & 31;   // col quad (active tx < 25)
    const int ty  = tid >> 5;   // warp id (0..7) -> rows 8*ty..8*ty+7

    for (int idx = tid; idx < DI_ * H_; idx += 256) {
        int j = idx / DI_;
        int i = idx - j * DI_;
        Wx_s[i * H_ + j] = Wx[idx];
    }

    float bv[4] = {0.f, 0.f, 0.f, 0.f};
    if (tx < 25) {
#pragma unroll
        for (int c = 0; c < 4; c++) bv[c] = bias[4 * tx + c];
    }

    unsigned sb[2];
    sb[0] = (unsigned)__cvta_generic_to_shared(inb0);
    sb[1] = (unsigned)__cvta_generic_to_shared(inb1);

    const int ntiles = (B_ * T_) / 64;   // 4096

    // Prologue: async-fill buffer 0 with this CTA's first tile
    int tile = blockIdx.x;
    if (tile < ntiles) {
        const int rbase = tile * 64;
        for (int idx = tid; idx < 64 * DI_; idx += 256) {
            int r = idx / DI_;
            int i = idx - r * DI_;
            cp_async4(sb[0] + 4u * (i * INS_STRIDE + r),
                      inp + (size_t)(rbase + r) * DI_ + i);
        }
    }
    asm volatile("cp.async.commit_group;");

    int buf = 0;
    for (; tile < ntiles; tile += gridDim.x) {
        const int nt = tile + gridDim.x;
        if (nt < ntiles) {
            const int rb2 = nt * 64;
            for (int idx = tid; idx < 64 * DI_; idx += 256) {
                int r = idx / DI_;
                int i = idx - r * DI_;
                cp_async4(sb[buf ^ 1] + 4u * (i * INS_STRIDE + r),
                          inp + (size_t)(rb2 + r) * DI_ + i);
            }
            asm volatile("cp.async.commit_group;");
            asm volatile("cp.async.wait_group 1;");
        } else {
            asm volatile("cp.async.wait_group 0;");
        }
        __syncthreads();   // current buffer ready for everyone

        const float* in_s = buf ? inb1 : inb0;
        const int rbase = tile * 64;

        if (tx < 25) {
            ull acc[4][4];
#pragma unroll
            for (int p = 0; p < 4; p++)
#pragma unroll
                for (int c = 0; c < 4; c++) acc[p][c] = dup2(bv[c]);

#pragma unroll 4
            for (int i = 0; i < DI_; i++) {
                ulonglong2 ap0 = *(const ulonglong2*)(in_s + i * INS_STRIDE + 8 * ty);
                ulonglong2 ap1 = *(const ulonglong2*)(in_s + i * INS_STRIDE + 8 * ty + 4);
                float4 wv = *(const float4*)(Wx_s + i * H_ + 4 * tx);
                ull w0 = dup2(wv.x), w1 = dup2(wv.y), w2 = dup2(wv.z), w3 = dup2(wv.w);
                acc[0][0] = fma2(ap0.x, w0, acc[0][0]);
                acc[0][1] = fma2(ap0.x, w1, acc[0][1]);
                acc[0][2] = fma2(ap0.x, w2, acc[0][2]);
                acc[0][3] = fma2(ap0.x, w3, acc[0][3]);
                acc[1][0] = fma2(ap0.y, w0, acc[1][0]);
                acc[1][1] = fma2(ap0.y, w1, acc[1][1]);
                acc[1][2] = fma2(ap0.y, w2, acc[1][2]);
                acc[1][3] = fma2(ap0.y, w3, acc[1][3]);
                acc[2][0] = fma2(ap1.x, w0, acc[2][0]);
                acc[2][1] = fma2(ap1.x, w1, acc[2][1]);
                acc[2][2] = fma2(ap1.x, w2, acc[2][2]);
                acc[2][3] = fma2(ap1.x, w3, acc[2][3]);
                acc[3][0] = fma2(ap1.y, w0, acc[3][0]);
                acc[3][1] = fma2(ap1.y, w1, acc[3][1]);
                acc[3][2] = fma2(ap1.y, w2, acc[3][2]);
                acc[3][3] = fma2(ap1.y, w3, acc[3][3]);
            }
#pragma unroll
            for (int p = 0; p < 4; p++) {
                float2 c0 = u2f(acc[p][0]);
                float2 c1 = u2f(acc[p][1]);
                float2 c2 = u2f(acc[p][2]);
                float2 c3 = u2f(acc[p][3]);
                int re = rbase + 8 * ty + 2 * p;
                float4 oe; oe.x = c0.x; oe.y = c1.x; oe.z = c2.x; oe.w = c3.x;
                float4 oo; oo.x = c0.y; oo.y = c1.y; oo.z = c2.y; oo.w = c3.y;
                *(float4*)(g_xp + (size_t)re * H_ + 4 * tx)       = oe;
                *(float4*)(g_xp + (size_t)(re + 1) * H_ + 4 * tx) = oo;
            }
        }
        __syncthreads();   // everyone done reading buf before it is refilled
        buf ^= 1;
    }
}

// ---------------------------------------------------------------------------
// Kernel B: sequential scan. 512 CTAs x 128 threads, ONE chain per CTA,
// 4 CTAs resident per SM -> 4 warps/SMSP from 4 independent barrier domains
// (one CTA's tanh/barrier tail is filled by the other CTAs' FFMA2).
// Thread: warp w, lane -> j = 25*w + lane (lane<25). W row j in 50 packed
// b64 regs; h (100 floats) double-buffered in smem, read as b64 pairs.
// xp/noise prefetched 2 steps ahead. Fast exact tanh via __expf.
// ---------------------------------------------------------------------------
__global__ void __launch_bounds__(128, 4) scan_kernel(
    const float* __restrict__ noise,   // [B, T, H]
    const float* __restrict__ Wh,      // [H, H]
    const float* __restrict__ ah0,     // [H]
    float* __restrict__ hstore)        // [B, T, H]
{
    __shared__ __align__(16) float hs[2][104];

    const int tid  = threadIdx.x;
    const int lane = tid & 31;
    const int w    = tid >> 5;             // 0..3
    const int j    = 25 * w + lane;        // hidden unit
    const bool act = lane < 25;

    // W row j -> 50 packed b64 regs
    ull wk[50];
    if (act) {
        const ulonglong2* wr = (const ulonglong2*)(Wh + j * H_);
#pragma unroll
        for (int kk = 0; kk < 25; kk++) {
            ulonglong2 v = wr[kk];
            wk[2 * kk]     = v.x;
            wk[2 * kk + 1] = v.y;
        }
    }

    float ah = 0.f;
    if (act) {
        ah = ah0[j];
        hs[0][j] = tanhf(fmaxf(ah, 0.f));
    }

    // per-thread linear offset into [B,T,H] tensors (chain = blockIdx.x)
    int idx = blockIdx.x * (T_ * H_) + j;

    // prefetch ring, depth 2
    float xc = 0.f, nc = 0.f, xn = 0.f, nn = 0.f;
    if (act) {
        xc = g_xp[idx];        nc = noise[idx];
        xn = g_xp[idx + H_];   nn = noise[idx + H_];
    }
    __syncthreads();

    int buf = 0;
    for (int t = 0; t < T_; t++) {
        // prefetch t+2
        float px = 0.f, pn = 0.f;
        if (act && t + 2 < T_) {
            px = g_xp[idx + 2 * H_];
            pn = noise[idx + 2 * H_];
        }

        if (act) {
            const ulonglong2* h4 = (const ulonglong2*)hs[buf];
            ull a = 0, b = 0;   // bit pattern 0 == packed (0.f, 0.f)
#pragma unroll
            for (int kk = 0; kk < 25; kk++) {
                ulonglong2 v = h4[kk];
                a = fma2(v.x, wk[2 * kk],     a);
                b = fma2(v.y, wk[2 * kk + 1], b);
            }
            float2 sa = u2f(a), sb = u2f(b);
            float sum = (sa.x + sa.y) + (sb.x + sb.y);

            ah = fmaf(0.1f, (sum + xc) - ah, ah);
            float x = fmaxf(ah, 0.f);
            float e = __expf(-2.f * x);
            float h = __fdividef(1.f - e, 1.f + e) + nc;
            hs[buf ^ 1][j] = h;
            hstore[idx] = h;
        }
        xc = xn; nc = nn; xn = px; nn = pn;
        idx += H_;
        buf ^= 1;
        __syncthreads();
    }
}

// ---------------------------------------------------------------------------
// Kernel C: output[r][d] = sum_j hstore[r][j] * W_y[d][j]
// ---------------------------------------------------------------------------
__global__ void __launch_bounds__(256) outproj_kernel(
    const float* __restrict__ hst,   // [B*T, H]
    const float* __restrict__ Wy,    // [DO, H]
    float* __restrict__ out)         // [B*T, DO]
{
    __shared__ float wy_s[DO_ * H_];
    const int tid = threadIdx.x;
    for (int idx = tid; idx < DO_ * H_; idx += 256) wy_s[idx] = Wy[idx];
    __syncthreads();

    const int lane = tid & 31;
    const int w    = tid >> 5;
    const size_t row = (size_t)blockIdx.x * 8 + w;

    float a0 = 0.f, a1 = 0.f;
    for (int j = lane; j < H_; j += 32) {
        float h = hst[row * H_ + j];
        a0 = fmaf(h, wy_s[j],      a0);
        a1 = fmaf(h, wy_s[H_ + j], a1);
    }
#pragma unroll
    for (int off = 16; off > 0; off >>= 1) {
        a0 += __shfl_down_sync(0xffffffffu, a0, off);
        a1 += __shfl_down_sync(0xffffffffu, a1, off);
    }
    if (lane == 0) {
        out[row * DO_ + 0] = a0;
        out[row * DO_ + 1] = a1;
    }
}

// ---------------------------------------------------------------------------
extern "C" void kernel_launch(void* const* d_in, const int* in_sizes, int n_in,
                              void* d_out, int out_size)
{
    const float* inp   = (const float*)d_in[0];  // [B,T,DI]
    const float* noise = (const float*)d_in[1];  // [B,T,H]
    const float* Wx    = (const float*)d_in[2];  // [H,DI]
    const float* bias  = (const float*)d_in[3];  // [H]
    const float* Wh    = (const float*)d_in[4];  // [H,H]
    const float* Wy    = (const float*)d_in[5];  // [DO,H]
    const float* ah0   = (const float*)d_in[6];  // [H]

    float* out    = (float*)d_out;                  // [B,T,DO] first
    float* hstore = out + (size_t)B_ * T_ * DO_;    // [B,T,H] second

    const int xp_smem = (DI_ * H_ + 2 * DI_ * INS_STRIDE) * (int)sizeof(float); // 95344 B
    static int attr_done = 0;
    if (!attr_done) {
        cudaFuncSetAttribute(xp_gemm_kernel,
                             cudaFuncAttributeMaxDynamicSharedMemorySize, xp_smem);
        attr_done = 1;
    }

    xp_gemm_kernel<<<1024, 256, xp_smem>>>(inp, Wx, bias);
    scan_kernel<<<B_, 128>>>(noise, Wh, ah0, hstore);
    outproj_kernel<<<(B_ * T_) / 8, 256>>>(hstore, Wy, out);
}

// round 7
// speedup vs baseline: 1.0607x; 1.0607x over previous
#include <cuda_runtime.h>
#include <math.h>

#define B_  512
#define T_  512
#define H_  100
#define DI_ 101
#define DO_ 2

typedef unsigned long long ull;

__device__ float g_xp[(size_t)B_ * T_ * H_];   // holds 0.1*(inp@Wx^T + b)

__device__ __forceinline__ ull fma2(ull a, ull b, ull c) {
    ull d;
    asm("fma.rn.f32x2 %0, %1, %2, %3;" : "=l"(d) : "l"(a), "l"(b), "l"(c));
    return d;
}
__device__ __forceinline__ ull add2(ull a, ull b) {
    ull d;
    asm("add.rn.f32x2 %0, %1, %2;" : "=l"(d) : "l"(a), "l"(b));
    return d;
}
__device__ __forceinline__ ull dup2(float a) {
    ull d;
    asm("mov.b64 %0, {%1, %1};" : "=l"(d) : "f"(a));
    return d;
}
__device__ __forceinline__ float2 u2f(ull v) {
    float2 f;
    asm("mov.b64 {%0, %1}, %2;" : "=f"(f.x), "=f"(f.y) : "l"(v));
    return f;
}
__device__ __forceinline__ void cp_async4(unsigned smem_addr, const void* gptr) {
    asm volatile("cp.async.ca.shared.global [%0], [%1], 4;"
                 :: "r"(smem_addr), "l"(gptr));
}

// ---------------------------------------------------------------------------
// Kernel A: g_xp[r][j] = 0.1 * (sum_i input[r][i] * W_x[j][i] + b[j])
// Round-5 synchronous structure (best measured). launch_bounds(256,3) +
// carveout to allow 3 CTAs/SM (3 x 67.9KB smem fits in 228KB).
// ---------------------------------------------------------------------------
#define INS_STRIDE 68
__global__ void __launch_bounds__(256, 3) xp_gemm_kernel(
    const float* __restrict__ inp,   // [B*T, DI]
    const float* __restrict__ Wx,    // [H, DI]
    const float* __restrict__ bias)  // [H]
{
    extern __shared__ __align__(16) float smem[];
    float* Wx_s = smem;                 // [i][j]  DI_*H_ floats (pre-scaled 0.1)
    float* in_s = smem + DI_ * H_;      // [i][r]  DI_*INS_STRIDE floats

    const int tid = threadIdx.x;
    const int tx  = tid & 31;   // col quad (active tx < 25)
    const int ty  = tid >> 5;   // warp id (0..7) -> rows 8*ty..8*ty+7

    for (int idx = tid; idx < DI_ * H_; idx += 256) {
        int j = idx / DI_;
        int i = idx - j * DI_;
        Wx_s[i * H_ + j] = 0.1f * Wx[idx];
    }

    float bv[4] = {0.f, 0.f, 0.f, 0.f};
    if (tx < 25) {
#pragma unroll
        for (int c = 0; c < 4; c++) bv[c] = 0.1f * bias[4 * tx + c];
    }

    const int ntiles = (B_ * T_) / 64;   // 4096
    for (int tile = blockIdx.x; tile < ntiles; tile += gridDim.x) {
        __syncthreads();
        const int rbase = tile * 64;
        for (int idx = tid; idx < 64 * DI_; idx += 256) {
            int r = idx / DI_;
            int i = idx - r * DI_;
            in_s[i * INS_STRIDE + r] = inp[(size_t)(rbase + r) * DI_ + i];
        }
        __syncthreads();

        if (tx < 25) {
            ull acc[4][4];
#pragma unroll
            for (int p = 0; p < 4; p++)
#pragma unroll
                for (int c = 0; c < 4; c++) acc[p][c] = dup2(bv[c]);

#pragma unroll 4
            for (int i = 0; i < DI_; i++) {
                ulonglong2 ap0 = *(const ulonglong2*)(in_s + i * INS_STRIDE + 8 * ty);
                ulonglong2 ap1 = *(const ulonglong2*)(in_s + i * INS_STRIDE + 8 * ty + 4);
                float4 wv = *(const float4*)(Wx_s + i * H_ + 4 * tx);
                ull w0 = dup2(wv.x), w1 = dup2(wv.y), w2 = dup2(wv.z), w3 = dup2(wv.w);
                acc[0][0] = fma2(ap0.x, w0, acc[0][0]);
                acc[0][1] = fma2(ap0.x, w1, acc[0][1]);
                acc[0][2] = fma2(ap0.x, w2, acc[0][2]);
                acc[0][3] = fma2(ap0.x, w3, acc[0][3]);
                acc[1][0] = fma2(ap0.y, w0, acc[1][0]);
                acc[1][1] = fma2(ap0.y, w1, acc[1][1]);
                acc[1][2] = fma2(ap0.y, w2, acc[1][2]);
                acc[1][3] = fma2(ap0.y, w3, acc[1][3]);
                acc[2][0] = fma2(ap1.x, w0, acc[2][0]);
                acc[2][1] = fma2(ap1.x, w1, acc[2][1]);
                acc[2][2] = fma2(ap1.x, w2, acc[2][2]);
                acc[2][3] = fma2(ap1.x, w3, acc[2][3]);
                acc[3][0] = fma2(ap1.y, w0, acc[3][0]);
                acc[3][1] = fma2(ap1.y, w1, acc[3][1]);
                acc[3][2] = fma2(ap1.y, w2, acc[3][2]);
                acc[3][3] = fma2(ap1.y, w3, acc[3][3]);
            }
#pragma unroll
            for (int p = 0; p < 4; p++) {
                float2 c0 = u2f(acc[p][0]);
                float2 c1 = u2f(acc[p][1]);
                float2 c2 = u2f(acc[p][2]);
                float2 c3 = u2f(acc[p][3]);
                int re = rbase + 8 * ty + 2 * p;
                float4 oe; oe.x = c0.x; oe.y = c1.x; oe.z = c2.x; oe.w = c3.x;
                float4 oo; oo.x = c0.y; oo.y = c1.y; oo.z = c2.y; oo.w = c3.y;
                *(float4*)(g_xp + (size_t)re * H_ + 4 * tx)       = oe;
                *(float4*)(g_xp + (size_t)(re + 1) * H_ + 4 * tx) = oo;
            }
        }
    }
}

// ---------------------------------------------------------------------------
// Kernel B: sequential scan. 512 CTAs x 128 threads, 1 chain/CTA, occ 4.
// - wk = 0.1*W row in 50 packed b64 regs (no other big reg arrays -> no spill)
// - xp/noise staged via depth-4 cp.async smem ring (frees prefetch registers)
// - clock64 stagger de-phases the 4 co-resident CTAs so serial tails overlap
//   with other CTAs' matvec issue.
// ---------------------------------------------------------------------------
__global__ void __launch_bounds__(128, 4) scan_kernel(
    const float* __restrict__ noise,   // [B, T, H]
    const float* __restrict__ Wh,      // [H, H]
    const float* __restrict__ ah0,     // [H]
    float* __restrict__ hstore)        // [B, T, H]
{
    __shared__ __align__(16) float hs[2][104];
    __shared__ __align__(16) float rxp[4][100];
    __shared__ __align__(16) float rnz[4][100];

    const int tid  = threadIdx.x;
    const int lane = tid & 31;
    const int w    = tid >> 5;             // 0..3
    const int j    = 25 * w + lane;        // hidden unit
    const bool act = lane < 25;

    // De-phase co-resident CTAs (timing only; no effect on results)
    {
        long long lim = (long long)((blockIdx.x & 3) * 256);
        long long s0 = clock64();
        while (clock64() - s0 < lim) {}
    }

    // 0.1 * W row j -> 50 packed b64 regs
    ull wk[50];
    if (act) {
        const float2* wr = (const float2*)(Wh + j * H_);
#pragma unroll
        for (int kk = 0; kk < 50; kk++) {
            float2 v = wr[kk];
            float2 s; s.x = 0.1f * v.x; s.y = 0.1f * v.y;
            wk[kk] = *(ull*)&s;
        }
    }

    float ah = 0.f;
    if (act) {
        ah = ah0[j];
        hs[0][j] = tanhf(fmaxf(ah, 0.f));
    }

    const float* xp_src = g_xp  + (size_t)blockIdx.x * (T_ * H_) + j;
    const float* nz_src = noise + (size_t)blockIdx.x * (T_ * H_) + j;
    float* hst = hstore + (size_t)blockIdx.x * (T_ * H_) + j;

    unsigned rxp_a = (unsigned)__cvta_generic_to_shared(rxp);
    unsigned rnz_a = (unsigned)__cvta_generic_to_shared(rnz);

    // Prologue: prefetch t = 0,1,2 (3 groups)
#pragma unroll
    for (int p = 0; p < 3; p++) {
        if (act) {
            cp_async4(rxp_a + 4u * (p * 100 + j), xp_src + (size_t)p * H_);
            cp_async4(rnz_a + 4u * (p * 100 + j), nz_src + (size_t)p * H_);
        }
        asm volatile("cp.async.commit_group;");
    }
    __syncthreads();

    int buf = 0;
    for (int t = 0; t < T_; t++) {
        // prefetch t+3 into slot (t+3)&3 (this thread is the sole consumer)
        if (act && t + 3 < T_) {
            int s = (t + 3) & 3;
            cp_async4(rxp_a + 4u * (s * 100 + j), xp_src + (size_t)(t + 3) * H_);
            cp_async4(rnz_a + 4u * (s * 100 + j), nz_src + (size_t)(t + 3) * H_);
        }
        asm volatile("cp.async.commit_group;");
        asm volatile("cp.async.wait_group 3;");   // group t complete

        if (act) {
            float xpv = rxp[t & 3][j];
            float nzv = rnz[t & 3][j];

            const ulonglong2* h4 = (const ulonglong2*)hs[buf];
            ull a = 0, b = 0;
#pragma unroll
            for (int kk = 0; kk < 25; kk++) {
                ulonglong2 v = h4[kk];
                a = fma2(v.x, wk[2 * kk],     a);
                b = fma2(v.y, wk[2 * kk + 1], b);
            }
            float2 s = u2f(add2(a, b));
            float sum = s.x + s.y;                  // = 0.1 * (h @ W^T)_j

            ah = fmaf(0.9f, ah, sum + xpv);         // xpv already 0.1*(xp+b)
            float x = fmaxf(ah, 0.f);
            float e = __expf(-2.f * x);
            float h = __fdividef(1.f - e, 1.f + e) + nzv;
            hs[buf ^ 1][j] = h;
            hst[(size_t)t * H_] = h;
        }
        buf ^= 1;
        __syncthreads();
    }
}

// ---------------------------------------------------------------------------
// Kernel C: output[r][d] = sum_j hstore[r][j] * W_y[d][j]
// ---------------------------------------------------------------------------
__global__ void __launch_bounds__(256) outproj_kernel(
    const float* __restrict__ hst,   // [B*T, H]
    const float* __restrict__ Wy,    // [DO, H]
    float* __restrict__ out)         // [B*T, DO]
{
    __shared__ float wy_s[DO_ * H_];
    const int tid = threadIdx.x;
    for (int idx = tid; idx < DO_ * H_; idx += 256) wy_s[idx] = Wy[idx];
    __syncthreads();

    const int lane = tid & 31;
    const int w    = tid >> 5;
    const size_t row = (size_t)blockIdx.x * 8 + w;

    float a0 = 0.f, a1 = 0.f;
    for (int j = lane; j < H_; j += 32) {
        float h = hst[row * H_ + j];
        a0 = fmaf(h, wy_s[j],      a0);
        a1 = fmaf(h, wy_s[H_ + j], a1);
    }
#pragma unroll
    for (int off = 16; off > 0; off >>= 1) {
        a0 += __shfl_down_sync(0xffffffffu, a0, off);
        a1 += __shfl_down_sync(0xffffffffu, a1, off);
    }
    if (lane == 0) {
        out[row * DO_ + 0] = a0;
        out[row * DO_ + 1] = a1;
    }
}

// ---------------------------------------------------------------------------
extern "C" void kernel_launch(void* const* d_in, const int* in_sizes, int n_in,
                              void* d_out, int out_size)
{
    const float* inp   = (const float*)d_in[0];  // [B,T,DI]
    const float* noise = (const float*)d_in[1];  // [B,T,H]
    const float* Wx    = (const float*)d_in[2];  // [H,DI]
    const float* bias  = (const float*)d_in[3];  // [H]
    const float* Wh    = (const float*)d_in[4];  // [H,H]
    const float* Wy    = (const float*)d_in[5];  // [DO,H]
    const float* ah0   = (const float*)d_in[6];  // [H]

    float* out    = (float*)d_out;                  // [B,T,DO] first
    float* hstore = out + (size_t)B_ * T_ * DO_;    // [B,T,H] second

    const int xp_smem = (DI_ * H_ + DI_ * INS_STRIDE) * (int)sizeof(float);  // 67872 B
    static int attr_done = 0;
    if (!attr_done) {
        cudaFuncSetAttribute(xp_gemm_kernel,
                             cudaFuncAttributeMaxDynamicSharedMemorySize, xp_smem);
        cudaFuncSetAttribute(xp_gemm_kernel,
                             cudaFuncAttributePreferredSharedMemoryCarveout,
                             cudaSharedmemCarveoutMaxShared);
        attr_done = 1;
    }

    xp_gemm_kernel<<<1024, 256, xp_smem>>>(inp, Wx, bias);
    scan_kernel<<<B_, 128>>>(noise, Wh, ah0, hstore);
    outproj_kernel<<<(B_ * T_) / 8, 256>>>(hstore, Wy, out);
}